// round 8
// baseline (speedup 1.0000x reference)
#include <cuda_runtime.h>
#include <cstdint>

// Problem constants
#define BB 256      // batch
#define TT 512      // timesteps
#define DD 128      // input dim
#define HH 512      // hidden
#define KKTOT 640   // D + H fused K per step
#define CC 10       // classes

// Tiling
#define M_BLK 64            // batch rows per CTA
#define NH_BLK 16           // h-columns per CTA
#define NG_BLK 64           // gate columns per CTA
#define NT_N (HH / NH_BLK)  // 32
#define NT_M (BB / M_BLK)   // 4
#define GRID_SZ (NT_M * NT_N)  // 128 CTAs, all co-resident
#define NTHR 512            // 4 k-groups x 128 threads -> 4 warps/SMSP
#define NGRP 4
#define KQ (KKTOT / NGRP)   // 160 K per group
#define KC 16               // k-chunk (10 chunks/group/step)

#define WS_PAD 68                      // padded row stride (floats)
#define WS_FLOATS (KKTOT * WS_PAD)     // 43520 floats = 174,080 B
#define ZBUF_FLOATS (KC * WS_PAD)      // 1088 floats
// 8 Z buffers (2 per group) = 34,816 B; total smem = 209,152 B

// Persistent device state
__device__ float g_h[2][BB * HH];               // h ping-pong
__device__ float g_partial[NT_N][BB][CC];       // partial logits
struct __align__(128) Bar { unsigned count; unsigned gen; unsigned pad[30]; };
__device__ Bar g_mbar[NT_M];                    // per-mtile barriers (32 CTAs each)
__device__ Bar g_fbar;                          // final barrier

// ---------------- per-mtile barrier (32 CTAs) -------------------------------
__device__ __forceinline__ void mtile_barrier(int mt) {
    __threadfence();
    __syncthreads();
    if (threadIdx.x == 0) {
        unsigned old = *((volatile unsigned*)&g_mbar[mt].gen);  // read BEFORE arrive
        unsigned a = atomicAdd(&g_mbar[mt].count, 1u);
        if (a == NT_N - 1u) {
            atomicExch(&g_mbar[mt].count, 0u);
            __threadfence();
            atomicAdd(&g_mbar[mt].gen, 1u);
        } else {
            while (*((volatile unsigned*)&g_mbar[mt].gen) == old) { }
        }
    }
    __syncthreads();
}

// ---------------- packed fp32x2 ops ----------------------------------------
__device__ __forceinline__ void fma2(unsigned long long& acc,
                                     unsigned long long a,
                                     unsigned long long b) {
    asm("fma.rn.f32x2 %0, %1, %2, %0;" : "+l"(acc) : "l"(a), "l"(b));
}
__device__ __forceinline__ unsigned long long add2(unsigned long long a,
                                                   unsigned long long b) {
    unsigned long long r;
    asm("add.rn.f32x2 %0, %1, %2;" : "=l"(r) : "l"(a), "l"(b));
    return r;
}
__device__ __forceinline__ unsigned long long pack2(float v) {
    unsigned long long r;
    unsigned u = __float_as_uint(v);
    asm("mov.b64 %0, {%1, %1};" : "=l"(r) : "r"(u));
    return r;
}

// ---------------- fast activations (MUFU tanh) -----------------------------
__device__ __forceinline__ float fast_tanh(float x) {
    float y;
    asm("tanh.approx.f32 %0, %1;" : "=f"(y) : "f"(x));
    return y;
}
__device__ __forceinline__ float fast_sigmoid(float x) {
    return 0.5f * fast_tanh(0.5f * x) + 0.5f;
}

// ---------------- Z tile staging (per group: 128 thr x 8 floats/chunk) -----
// Z row m = concat(X[b,t,:], h_prev[b,:]) staged transposed Zs[k][m].
// Thread: m = lidx&63, kb = (lidx>>6)*8 -> 8 consecutive k (8-aligned, never
// straddles the X/h boundary at k=128).
__device__ __forceinline__ void load_z8(const float* __restrict__ X,
                                        const float* __restrict__ hprev,
                                        int m0, int t, int kg0, int m,
                                        float4& v0, float4& v1) {
    if (kg0 < DD) {
        const float* s = X + ((size_t)(m0 + m) * TT + t) * DD + kg0;
        v0 = __ldg((const float4*)s);
        v1 = __ldg((const float4*)(s + 4));
    } else {
        const float* s = hprev + (size_t)(m0 + m) * HH + (kg0 - DD);
        v0 = __ldcg((const float4*)s);
        v1 = __ldcg((const float4*)(s + 4));
    }
}
__device__ __forceinline__ void sts_z8(float* zs, int kb, int m,
                                       float4 v0, float4 v1) {
    float* p = zs + kb * WS_PAD + m;    // lanes have consecutive m -> conflict-free
    p[0 * WS_PAD] = v0.x; p[1 * WS_PAD] = v0.y; p[2 * WS_PAD] = v0.z; p[3 * WS_PAD] = v0.w;
    p[4 * WS_PAD] = v1.x; p[5 * WS_PAD] = v1.y; p[6 * WS_PAD] = v1.z; p[7 * WS_PAD] = v1.w;
}

// ---------------- single fused kernel --------------------------------------
__global__ void __launch_bounds__(NTHR, 1)
lstm_all(const float* __restrict__ X,
         const float* __restrict__ W_ih,
         const float* __restrict__ W_hh,
         const float* __restrict__ b_ih,
         const float* __restrict__ b_hh,
         const float* __restrict__ W_lin,
         const float* __restrict__ b_lin,
         float* __restrict__ out)
{
    extern __shared__ float smem[];
    float* Ws  = smem;                            // [KKTOT][WS_PAD]
    float* Zb  = smem + WS_FLOATS;                // 8 x [KC][WS_PAD]
    float* bsm = Zb + 2 * NGRP * ZBUF_FLOATS;     // [NG_BLK]

    const int tid   = threadIdx.x;
    const int cta   = blockIdx.x;
    const int mtile = cta >> 5;
    const int ntile = cta & (NT_N - 1);
    const int m0    = mtile * M_BLK;
    const int c0    = ntile * NH_BLK;

    const int grp   = tid >> 7;                   // 0..3
    const int lidx  = tid & 127;
    const int tx    = lidx & 15;                  // h-column within tile
    const int ty    = lidx >> 4;                  // 0..7; rows ty*8..ty*8+7
    const int kbase = grp * KQ;

    const int sm  = lidx & 63;                    // staging column m
    const int skb = (lidx >> 6) * 8;              // staging k offset in chunk
    float* Zg = Zb + grp * (2 * ZBUF_FLOATS);

    // ---- one-time: W slice into SMEM; column n = 4*j + g, r = g*H + c0 + j
    for (int idx = tid; idx < NG_BLK * KKTOT; idx += NTHR) {
        int k = idx >> 6;
        int n = idx & 63;
        int j = n >> 2, g = n & 3;
        int r = g * HH + c0 + j;
        float v = (k < DD) ? W_ih[r * DD + k] : W_hh[r * HH + (k - DD)];
        Ws[k * WS_PAD + n] = v;
    }
    if (tid < NG_BLK) {
        int j = tid >> 2, g = tid & 3;
        int r = g * HH + c0 + j;
        bsm[tid] = b_ih[r] + b_hh[r];
    }
    // zero this CTA's 2 mtile-local h rows in ping buffer 0
    {
        float* p = &g_h[0][(size_t)(m0 + ntile * 2) * HH];
        for (int i = tid; i < 2 * HH; i += NTHR) p[i] = 0.f;
    }
    __syncthreads();

    float bias_r[4];
#pragma unroll
    for (int g = 0; g < 4; g++) bias_r[g] = bsm[tx * 4 + g];

    mtile_barrier(mtile);   // h0 zeros + W loads (all mtile-local deps)

    unsigned long long acc2[4][4];                // [row-pair][gate]
    float c_st[4], hsum[4];                       // groups 0 & 2 hold state
#pragma unroll
    for (int i = 0; i < 4; i++) { c_st[i] = 0.f; hsum[i] = 0.f; }

    unsigned long long* red = (unsigned long long*)Zb;   // 4352 ull available

    for (int t = 0; t < TT; t++) {
        const float* hprev = g_h[t & 1];
        float* hnext = g_h[(t + 1) & 1];
#pragma unroll
        for (int p = 0; p < 4; p++)
#pragma unroll
            for (int j = 0; j < 4; j++) acc2[p][j] = 0ull;

        float4 v0, v1;
        load_z8(X, hprev, m0, t, kbase + skb, sm, v0, v1);
        sts_z8(Zg, skb, sm, v0, v1);
        __syncthreads();

#pragma unroll 1
        for (int kc = 0; kc < KQ; kc += KC) {
            const float* cur = Zg + ((kc >> 4) & 1) * ZBUF_FLOATS;
            float* nxt       = Zg + (((kc >> 4) + 1) & 1) * ZBUF_FLOATS;
            const bool more = (kc + KC) < KQ;
            if (more) load_z8(X, hprev, m0, t, kbase + kc + KC + skb, sm, v0, v1);

            const float* wrow = Ws + (kbase + kc) * WS_PAD + (tx << 2);
#pragma unroll
            for (int kk = 0; kk < KC; kk++) {
                const float4 wv = *reinterpret_cast<const float4*>(wrow + kk * WS_PAD);
                unsigned long long w0 = pack2(wv.x), w1 = pack2(wv.y),
                                   w2 = pack2(wv.z), w3 = pack2(wv.w);
                const float* zr = cur + kk * WS_PAD + (ty << 3);
                const ulonglong2 za = *reinterpret_cast<const ulonglong2*>(zr);
                const ulonglong2 zc = *reinterpret_cast<const ulonglong2*>(zr + 4);
                fma2(acc2[0][0], za.x, w0); fma2(acc2[0][1], za.x, w1);
                fma2(acc2[0][2], za.x, w2); fma2(acc2[0][3], za.x, w3);
                fma2(acc2[1][0], za.y, w0); fma2(acc2[1][1], za.y, w1);
                fma2(acc2[1][2], za.y, w2); fma2(acc2[1][3], za.y, w3);
                fma2(acc2[2][0], zc.x, w0); fma2(acc2[2][1], zc.x, w1);
                fma2(acc2[2][2], zc.x, w2); fma2(acc2[2][3], zc.x, w3);
                fma2(acc2[3][0], zc.y, w0); fma2(acc2[3][1], zc.y, w1);
                fma2(acc2[3][2], zc.y, w2); fma2(acc2[3][3], zc.y, w3);
            }
            if (more) sts_z8(nxt, skb, sm, v0, v1);
            __syncthreads();
        }

        // ---- 2-stage k-reduction: (g1->g0, g3->g2) then cross-exchange -----
        if (grp == 1) {
#pragma unroll
            for (int p = 0; p < 4; p++)
#pragma unroll
                for (int j = 0; j < 4; j++)
                    red[(p * 4 + j) * 128 + lidx] = acc2[p][j];
        } else if (grp == 3) {
#pragma unroll
            for (int p = 0; p < 4; p++)
#pragma unroll
                for (int j = 0; j < 4; j++)
                    red[2048 + (p * 4 + j) * 128 + lidx] = acc2[p][j];
        }
        __syncthreads();
        if (grp == 0) {
#pragma unroll
            for (int p = 0; p < 4; p++)
#pragma unroll
                for (int j = 0; j < 4; j++)
                    acc2[p][j] = add2(acc2[p][j], red[(p * 4 + j) * 128 + lidx]);
        } else if (grp == 2) {
#pragma unroll
            for (int p = 0; p < 4; p++)
#pragma unroll
                for (int j = 0; j < 4; j++)
                    acc2[p][j] = add2(acc2[p][j], red[2048 + (p * 4 + j) * 128 + lidx]);
        }
        __syncthreads();
        // round 2: g0 sends pairs {2,3}; g2 sends pairs {0,1}
        if (grp == 0) {
#pragma unroll
            for (int p = 2; p < 4; p++)
#pragma unroll
                for (int j = 0; j < 4; j++)
                    red[1024 + ((p - 2) * 4 + j) * 128 + lidx] = acc2[p][j];
        } else if (grp == 2) {
#pragma unroll
            for (int p = 0; p < 2; p++)
#pragma unroll
                for (int j = 0; j < 4; j++)
                    red[(p * 4 + j) * 128 + lidx] = acc2[p][j];
        }
        __syncthreads();

        // ---- epilogue: g0 -> rows 0..3, g2 -> rows 4..7 --------------------
        if ((grp & 1) == 0) {
            const int pbase = grp;         // g0: pairs 0,1 ; g2: pairs 2,3
#pragma unroll
            for (int lp = 0; lp < 2; lp++) {
                const int p = pbase + lp;
                float ga[4][2];
#pragma unroll
                for (int j = 0; j < 4; j++) {
                    unsigned long long other = (grp == 0)
                        ? red[(p * 4 + j) * 128 + lidx]
                        : red[1024 + ((p - 2) * 4 + j) * 128 + lidx];
                    unsigned long long s = add2(acc2[p][j], other);
                    unsigned lo, hi;
                    asm("mov.b64 {%0, %1}, %2;" : "=r"(lo), "=r"(hi) : "l"(s));
                    ga[j][0] = __uint_as_float(lo) + bias_r[j];
                    ga[j][1] = __uint_as_float(hi) + bias_r[j];
                }
#pragma unroll
                for (int hf = 0; hf < 2; hf++) {
                    const int i = lp * 2 + hf;           // local state idx 0..3
                    float ig = fast_sigmoid(ga[0][hf]);
                    float fg = fast_sigmoid(ga[1][hf]);
                    float gg = fast_tanh(ga[2][hf]);
                    float og = fast_sigmoid(ga[3][hf]);
                    float cv = fg * c_st[i] + ig * gg;
                    c_st[i] = cv;
                    float hv = og * fast_tanh(cv);
                    hsum[i] += hv;
                    hnext[(size_t)(m0 + ty * 8 + 2 * p + hf) * HH + c0 + tx] = hv;
                }
            }
        }
        mtile_barrier(mtile);
    }

    // ---- logits partials (groups 0 & 2): shuffle-reduce over tx ------------
    const float inv_t = 1.f / (float)TT;
    if ((grp & 1) == 0) {
        const int rbase = (grp == 0) ? 0 : 4;
#pragma unroll
        for (int i = 0; i < 4; i++) {
            const int b = m0 + ty * 8 + rbase + i;
            const float hm = hsum[i] * inv_t;
#pragma unroll
            for (int cls = 0; cls < CC; cls++) {
                float v = hm * __ldg(&W_lin[cls * HH + c0 + tx]);
                v += __shfl_xor_sync(0xffffffffu, v, 8);
                v += __shfl_xor_sync(0xffffffffu, v, 4);
                v += __shfl_xor_sync(0xffffffffu, v, 2);
                v += __shfl_xor_sync(0xffffffffu, v, 1);
                if (tx == 0) g_partial[ntile][b][cls] = v;
            }
        }
    }

    // ---- final global arrive; CTA 0 reduces to logits ----------------------
    __threadfence();
    __syncthreads();
    if (tid == 0) {
        atomicAdd(&g_fbar.count, 1u);
        if (cta == 0) {
            while (*((volatile unsigned*)&g_fbar.count) < (unsigned)GRID_SZ) { }
            __threadfence();
        }
    }
    __syncthreads();
    if (cta == 0) {
        for (int idx = tid; idx < BB * CC; idx += NTHR) {
            int b = idx / CC, cls = idx % CC;
            float s = __ldg(&b_lin[cls]);
#pragma unroll
            for (int n = 0; n < NT_N; n++) s += __ldcg(&g_partial[n][b][cls]);
            out[idx] = s;
        }
        __syncthreads();
        if (tid == 0) atomicExch(&g_fbar.count, 0u);   // reset for next replay
    }
}

extern "C" void kernel_launch(void* const* d_in, const int* in_sizes, int n_in,
                              void* d_out, int out_size) {
    const float* X     = (const float*)d_in[0];
    const float* W_ih  = (const float*)d_in[1];
    const float* W_hh  = (const float*)d_in[2];
    const float* b_ih  = (const float*)d_in[3];
    const float* b_hh  = (const float*)d_in[4];
    const float* W_lin = (const float*)d_in[5];
    const float* b_lin = (const float*)d_in[6];

    const int smem_bytes =
        (WS_FLOATS + 2 * NGRP * ZBUF_FLOATS + NG_BLK) * (int)sizeof(float);
    cudaFuncSetAttribute(lstm_all,
                         cudaFuncAttributeMaxDynamicSharedMemorySize, smem_bytes);

    lstm_all<<<GRID_SZ, NTHR, smem_bytes>>>(X, W_ih, W_hh, b_ih, b_hh,
                                            W_lin, b_lin, (float*)d_out);
}

// round 14
// speedup vs baseline: 1.5065x; 1.5065x over previous
#include <cuda_runtime.h>
#include <cuda_bf16.h>
#include <cstdint>

#define BB 256
#define TT 512
#define DD 128
#define HH 512
#define CC 10

#define M_BLK 64
#define NG_BLK 64            // gate cols per CTA (16 h-cols)
#define NT_M 4
#define NT_N 32
#define GRID_SZ 128
#define NTHR 128             // 4 warps; warp tile 32m x 32n
#define NCHUNK 10            // K = 640 in chunks of 64

// SMEM layout (bytes)
#define OFF_BIAS 0
#define OFF_GATES 256                    // [64][68] f32
#define GSTRIDE 68
#define OFF_Z 17664                      // 2 buf x (hi,lo) x [64][72] bf16
#define SZB 144                          // Z row stride bytes (72 bf16)
#define Z_VER 9216
#define Z_BUF 18432
#define OFF_W 54528                      // (hi,lo) x [64][648] bf16
#define SWB 1296                         // W row stride bytes (648 bf16)
#define W_VER 82944
#define SMEM_TOTAL 220416

// Persistent device state
__device__ __nv_bfloat16 g_Xhi[(size_t)BB*TT*DD];
__device__ __nv_bfloat16 g_Xlo[(size_t)BB*TT*DD];
__device__ __nv_bfloat16 g_hbf[2][2][BB*HH];      // [ping][hi/lo]
__device__ float g_partial[NT_N][BB][CC];
struct __align__(128) Bar { unsigned count; unsigned gen; unsigned pad[30]; };
__device__ Bar g_mbar[NT_M];
__device__ Bar g_fbar;

__device__ __forceinline__ float fast_tanh(float x) {
    float y; asm("tanh.approx.f32 %0, %1;" : "=f"(y) : "f"(x)); return y;
}
__device__ __forceinline__ float fast_sigmoid(float x) {
    return 0.5f * fast_tanh(0.5f * x) + 0.5f;
}

// m16n8k16 bf16 MMA (base PTX, sm_80+; compiles for compute_103)
__device__ __forceinline__ void mma16816(float* d, const uint32_t* a,
                                         const uint32_t* b) {
    asm volatile(
        "mma.sync.aligned.m16n8k16.row.col.f32.bf16.bf16.f32 "
        "{%0,%1,%2,%3}, {%4,%5,%6,%7}, {%8,%9}, {%0,%1,%2,%3};"
        : "+f"(d[0]), "+f"(d[1]), "+f"(d[2]), "+f"(d[3])
        : "r"(a[0]), "r"(a[1]), "r"(a[2]), "r"(a[3]), "r"(b[0]), "r"(b[1]));
}

__device__ __forceinline__ uint32_t bf2(float a, float b) {
    unsigned short ua = __bfloat16_as_ushort(__float2bfloat16(a));
    unsigned short ub = __bfloat16_as_ushort(__float2bfloat16(b));
    return (uint32_t)ua | ((uint32_t)ub << 16);
}

// ---- init: split X to bf16 hi/lo, zero h ping 0, reset barriers -----------
__global__ void lstm_init(const float* __restrict__ X) {
    size_t stride = (size_t)gridDim.x * blockDim.x;
    size_t i0 = (size_t)blockIdx.x * blockDim.x + threadIdx.x;
    const size_t NX = (size_t)BB * TT * DD;
    for (size_t i = i0; i < NX; i += stride) {
        float x = X[i];
        __nv_bfloat16 hi = __float2bfloat16(x);
        g_Xhi[i] = hi;
        g_Xlo[i] = __float2bfloat16(x - __bfloat162float(hi));
    }
    __nv_bfloat16* hz = &g_hbf[0][0][0];
    for (size_t i = i0; i < (size_t)2 * BB * HH; i += stride)
        hz[i] = __float2bfloat16(0.f);
    if (i0 == 0) {
        for (int m = 0; m < NT_M; m++) { g_mbar[m].count = 0; g_mbar[m].gen = 0; }
        g_fbar.count = 0;
    }
}

// ---- main persistent kernel ------------------------------------------------
__global__ void __launch_bounds__(NTHR, 1)
lstm_mma(const float* __restrict__ W_ih,
         const float* __restrict__ W_hh,
         const float* __restrict__ b_ih,
         const float* __restrict__ b_hh,
         const float* __restrict__ W_lin,
         const float* __restrict__ b_lin,
         float* __restrict__ out)
{
    extern __shared__ char smem[];
    float* bsm   = (float*)(smem + OFF_BIAS);
    float* gates = (float*)(smem + OFF_GATES);

    const int tid   = threadIdx.x;
    const int lane  = tid & 31;
    const int w     = tid >> 5;
    const int g     = lane >> 2;          // fragment group row
    const int tig   = lane & 3;           // thread-in-group
    const int cta   = blockIdx.x;
    const int mtile = cta >> 5;
    const int ntile = cta & 31;
    const int m0    = mtile * M_BLK;
    const int c0    = ntile * 16;
    const int mtb   = (w & 1) * 32;       // warp m offset
    const int ntb   = (w >> 1) * 32;      // warp n offset
    const int sm    = tid & 63;           // staging row
    const int sver  = tid >> 6;           // staging version (0=hi,1=lo)

    // ---- one-time W staging: col n = g*16 + j <-> weight row r = g*H+c0+j
    for (int idx = tid; idx < NG_BLK * (DD + HH); idx += NTHR) {
        int n = idx / (DD + HH);
        int k = idx - n * (DD + HH);
        int gg = n >> 4, j = n & 15;
        int r = gg * HH + c0 + j;
        float wv = (k < DD) ? W_ih[r * DD + k] : W_hh[r * HH + (k - DD)];
        __nv_bfloat16 hi = __float2bfloat16(wv);
        __nv_bfloat16 lo = __float2bfloat16(wv - __bfloat162float(hi));
        *(__nv_bfloat16*)(smem + OFF_W + n * SWB + k * 2) = hi;
        *(__nv_bfloat16*)(smem + OFF_W + W_VER + n * SWB + k * 2) = lo;
    }
    if (tid < NG_BLK) {
        int gg = tid >> 4, j = tid & 15;
        int r = gg * HH + c0 + j;
        bsm[tid] = b_ih[r] + b_hh[r];
    }
    __syncthreads();

    float c_st[8], hsum[8];
#pragma unroll
    for (int j = 0; j < 8; j++) { c_st[j] = 0.f; hsum[j] = 0.f; }

    for (int t = 0; t < TT; t++) {
        const int ping = t & 1;
        float D[2][4][4];
#pragma unroll
        for (int mt = 0; mt < 2; mt++)
#pragma unroll
            for (int nt = 0; nt < 4; nt++)
#pragma unroll
                for (int q = 0; q < 4; q++) D[mt][nt][q] = 0.f;

        // ---- prefetch chunk 0 (X) ----
        uint4 v[8];
        {
            const __nv_bfloat16* xs = sver ? g_Xlo : g_Xhi;
            const uint4* s4 = (const uint4*)(xs + ((size_t)(m0 + sm) * TT + t) * DD);
#pragma unroll
            for (int i = 0; i < 8; i++) v[i] = __ldg(s4 + i);
            char* zd = smem + OFF_Z + sver * Z_VER + sm * SZB;
#pragma unroll
            for (int i = 0; i < 8; i++) *(uint4*)(zd + i * 16) = v[i];
        }
        __syncthreads();

#pragma unroll 1
        for (int c = 0; c < NCHUNK; c++) {
            const int buf = c & 1;
            if (c == 1 && t > 0) {       // h(t-1) must be published before chunk 2
                if (tid == 0) {
                    while ((int)(*(volatile unsigned*)&g_mbar[mtile].gen) < t) { }
                    __threadfence();
                }
                __syncthreads();
            }
            if (c < NCHUNK - 1) {        // LDG chunk c+1
                const int cn = c + 1;
                if (cn < 2) {
                    const __nv_bfloat16* xs = sver ? g_Xlo : g_Xhi;
                    const uint4* s4 = (const uint4*)
                        (xs + ((size_t)(m0 + sm) * TT + t) * DD + cn * 64);
#pragma unroll
                    for (int i = 0; i < 8; i++) v[i] = __ldg(s4 + i);
                } else {
                    const uint4* s4 = (const uint4*)
                        (&g_hbf[ping][sver][(size_t)(m0 + sm) * HH + (cn * 64 - DD)]);
#pragma unroll
                    for (int i = 0; i < 8; i++) v[i] = __ldcg(s4 + i);
                }
            }

            // ---- MMA on chunk c (4 k-steps of 16) ----
            {
                const char* zb = smem + OFF_Z + buf * Z_BUF + (mtb + g) * SZB + tig * 4;
                // FIX (R11): W pointer must advance by chunk: + c * 64 cols * 2B
                const char* wb = smem + OFF_W + (ntb + g) * SWB + c * 128 + tig * 4;
#pragma unroll
                for (int s = 0; s < 4; s++) {
                    uint32_t Ah[2][4], Al[2][4], Bh[4][2], Bl[4][2];
#pragma unroll
                    for (int mt = 0; mt < 2; mt++) {
                        const char* p = zb + s * 32 + mt * 2304;   // 16 rows * 144B
                        Ah[mt][0] = *(const uint32_t*)(p);
                        Ah[mt][1] = *(const uint32_t*)(p + 1152);  // +8 rows
                        Ah[mt][2] = *(const uint32_t*)(p + 16);    // +8 cols
                        Ah[mt][3] = *(const uint32_t*)(p + 1168);
                        Al[mt][0] = *(const uint32_t*)(p + Z_VER);
                        Al[mt][1] = *(const uint32_t*)(p + Z_VER + 1152);
                        Al[mt][2] = *(const uint32_t*)(p + Z_VER + 16);
                        Al[mt][3] = *(const uint32_t*)(p + Z_VER + 1168);
                    }
#pragma unroll
                    for (int nt = 0; nt < 4; nt++) {
                        const char* p = wb + s * 32 + nt * 10368;  // 8 rows * 1296B
                        Bh[nt][0] = *(const uint32_t*)(p);
                        Bh[nt][1] = *(const uint32_t*)(p + 16);
                        Bl[nt][0] = *(const uint32_t*)(p + W_VER);
                        Bl[nt][1] = *(const uint32_t*)(p + W_VER + 16);
                    }
#pragma unroll
                    for (int mt = 0; mt < 2; mt++)
#pragma unroll
                        for (int nt = 0; nt < 4; nt++) {
                            mma16816(D[mt][nt], Ah[mt], Bh[nt]);
                            mma16816(D[mt][nt], Ah[mt], Bl[nt]);
                            mma16816(D[mt][nt], Al[mt], Bh[nt]);
                        }
                }
            }
            __syncthreads();
            if (c < NCHUNK - 1) {        // STS chunk c+1
                char* zd = smem + OFF_Z + ((c + 1) & 1) * Z_BUF + sver * Z_VER + sm * SZB;
#pragma unroll
                for (int i = 0; i < 8; i++) *(uint4*)(zd + i * 16) = v[i];
            }
            __syncthreads();
        }

        // ---- D fragments -> gates SMEM ----
#pragma unroll
        for (int mt = 0; mt < 2; mt++)
#pragma unroll
            for (int nt = 0; nt < 4; nt++) {
                int row = mtb + mt * 16 + g;
                int col = ntb + nt * 8 + tig * 2;
                *(float2*)(gates + row * GSTRIDE + col) =
                    make_float2(D[mt][nt][0], D[mt][nt][1]);
                *(float2*)(gates + (row + 8) * GSTRIDE + col) =
                    make_float2(D[mt][nt][2], D[mt][nt][3]);
            }
        __syncthreads();

        // ---- epilogue: thread owns (row sm, h-cols jb..jb+7) ----
        {
            const int jb = sver * 8;
            const float* gr = gates + sm * GSTRIDE;
            const int pout = (t + 1) & 1;
            uint32_t hw[4], lw[4];
#pragma unroll
            for (int q = 0; q < 4; q++) {
                float hv2[2];
#pragma unroll
                for (int u = 0; u < 2; u++) {
                    const int jj = q * 2 + u;
                    const int j = jb + jj;
                    float iv = gr[j]        + bsm[j];
                    float fv = gr[16 + j]   + bsm[16 + j];
                    float gv = gr[32 + j]   + bsm[32 + j];
                    float ov = gr[48 + j]   + bsm[48 + j];
                    float ig = fast_sigmoid(iv);
                    float fg = fast_sigmoid(fv);
                    float gg = fast_tanh(gv);
                    float og = fast_sigmoid(ov);
                    float cv = fg * c_st[jj] + ig * gg;
                    c_st[jj] = cv;
                    float hv = og * fast_tanh(cv);
                    hsum[jj] += hv;
                    hv2[u] = hv;
                }
                hw[q] = bf2(hv2[0], hv2[1]);
                float r0 = hv2[0] - __bfloat162float(__float2bfloat16(hv2[0]));
                float r1 = hv2[1] - __bfloat162float(__float2bfloat16(hv2[1]));
                lw[q] = bf2(r0, r1);
            }
            size_t off = (size_t)(m0 + sm) * HH + c0 + jb;
            *(uint4*)(&g_hbf[pout][0][off]) = make_uint4(hw[0], hw[1], hw[2], hw[3]);
            *(uint4*)(&g_hbf[pout][1][off]) = make_uint4(lw[0], lw[1], lw[2], lw[3]);
        }
        __threadfence();
        __syncthreads();
        if (tid == 0) {
            unsigned a = atomicAdd(&g_mbar[mtile].count, 1u);
            if (a == NT_N - 1u) {
                atomicExch(&g_mbar[mtile].count, 0u);
                __threadfence();
                atomicAdd(&g_mbar[mtile].gen, 1u);
            }
        }
    }

    // ---- logits partials: combine the two j-halves via SMEM ----
    {
        const int jb = sver * 8;
        const float inv_t = 1.f / (float)TT;
        float pl[CC];
#pragma unroll
        for (int cls = 0; cls < CC; cls++) {
            float s = 0.f;
#pragma unroll
            for (int jj = 0; jj < 8; jj++)
                s += hsum[jj] * __ldg(&W_lin[cls * HH + c0 + jb + jj]);
            pl[cls] = s;
        }
        float* scr = gates;              // reuse as [64][16] scratch
        if (sver == 1) {
#pragma unroll
            for (int cls = 0; cls < CC; cls++) scr[sm * 16 + cls] = pl[cls];
        }
        __syncthreads();
        if (sver == 0) {
#pragma unroll
            for (int cls = 0; cls < CC; cls++)
                g_partial[ntile][m0 + sm][cls] = (pl[cls] + scr[sm * 16 + cls]) * inv_t;
        }
    }

    // ---- final global barrier; CTA 0 reduces ----
    __threadfence();
    __syncthreads();
    if (tid == 0) {
        atomicAdd(&g_fbar.count, 1u);
        if (cta == 0) {
            while (*(volatile unsigned*)&g_fbar.count < (unsigned)GRID_SZ) { }
            __threadfence();
        }
    }
    __syncthreads();
    if (cta == 0) {
        for (int idx = tid; idx < BB * CC; idx += NTHR) {
            int b = idx / CC, cls = idx % CC;
            float s = __ldg(&b_lin[cls]);
#pragma unroll
            for (int n = 0; n < NT_N; n++) s += __ldcg(&g_partial[n][b][cls]);
            out[idx] = s;
        }
    }
}

extern "C" void kernel_launch(void* const* d_in, const int* in_sizes, int n_in,
                              void* d_out, int out_size) {
    const float* X     = (const float*)d_in[0];
    const float* W_ih  = (const float*)d_in[1];
    const float* W_hh  = (const float*)d_in[2];
    const float* b_ih  = (const float*)d_in[3];
    const float* b_hh  = (const float*)d_in[4];
    const float* W_lin = (const float*)d_in[5];
    const float* b_lin = (const float*)d_in[6];

    lstm_init<<<512, 256>>>(X);
    cudaFuncSetAttribute(lstm_mma,
                         cudaFuncAttributeMaxDynamicSharedMemorySize, SMEM_TOTAL);
    lstm_mma<<<GRID_SZ, NTHR, SMEM_TOTAL>>>(W_ih, W_hh, b_ih, b_hh,
                                            W_lin, b_lin, (float*)d_out);
}